// round 13
// baseline (speedup 1.0000x reference)
#include <cuda_runtime.h>
#include <cstdint>
#include <math.h>

// Problem constants
#define BB 64
#define SS 1024
#define II 512
#define HH 512
#define NPANEL 128   // persistent CTAs: 64 panels per layer, 1 CTA/SM
#define JPC 8        // hidden units per CTA
#define TPB 256      // 8 warps; warp w owns k in [128w, 128w+128)
#define NWARP 8
#define KRANGE 128   // k per warp
#define KT 16        // k-chunk staged per warp
#define NCHUNK 8     // 128 / 16

#define WS_FLOATS (1024*32)      // duplicated weight panel [k][32]
#define ABUF_FLOATS (KT*64)      // 1024 floats per buffer
#define PX_ULL (NWARP*8*2*32)    // 4096 ull = 32KB partial-sum exchange
#define SMEM_BYTES ((WS_FLOATS + 2*NWARP*ABUF_FLOATS)*4 + PX_ULL*8)  // 229376 B

typedef unsigned long long ull;

// Scratch (device globals: allocation-free per harness rules)
__device__ float g_Wdup[NPANEL*1024*32];    // [panel][k][32]: per j-pair-group, dup pairs
__device__ float g_h0[4][BB*HH];            // 4-deep ring, layer-0 hidden (slot = s & 3)
__device__ float g_h1[2][BB*HH];            // ping-pong hidden, layer 1
__device__ unsigned g_c0;                   // layer-0 arrival counter (monotonic)
__device__ unsigned g_c1;                   // layer-1 arrival counter (monotonic)

__device__ __forceinline__ ull ffma2(ull a, ull b, ull c){
    ull d;
    asm("fma.rn.f32x2 %0, %1, %2, %3;" : "=l"(d) : "l"(a), "l"(b), "l"(c));
    return d;
}
__device__ __forceinline__ ull addf2(ull a, ull b){
    ull d;
    asm("add.rn.f32x2 %0, %1, %2;" : "=l"(d) : "l"(a), "l"(b));
    return d;
}
__device__ __forceinline__ void unpack2(ull v, float& lo, float& hi){
    asm("mov.b64 {%0, %1}, %2;" : "=f"(lo), "=f"(hi) : "l"(v));
}
__device__ __forceinline__ void wait_ge(unsigned* ctr, unsigned tgt){
    unsigned v;
    do {
        asm volatile("ld.acquire.gpu.global.u32 %0, [%1];"
                     : "=r"(v) : "l"(ctr) : "memory");
    } while (v < tgt);
}

// Build duplicated weight panels:
// panel p: layer l = p>>6, hidden units j0..j0+7 with j0 = (p&63)*8.
// Row k (32 floats): for jg in 0..3 (j-pair = 2jg, 2jg+1):
//   [wg_{2jg} x2, wc_{2jg} x2, wg_{2jg+1} x2, wc_{2jg+1} x2]
// where wg = Wg[l][k][j] (rows already [inp;h] ordered) and
//       wc = k<512 ? Wi[l][k][j] : Wh[l][k-512][j].
__global__ void prep_kernel(const float* __restrict__ Wg,
                            const float* __restrict__ Wi,
                            const float* __restrict__ Wh){
    int idx = blockIdx.x * blockDim.x + threadIdx.x;
    if (idx >= NPANEL*1024*32) return;
    int cc = idx & 31;
    int k  = (idx >> 5) & 1023;
    int p  = idx >> 15;
    int l  = p >> 6;
    int jg = cc >> 3;
    int within = cc & 7;
    int pairidx = within >> 1;           // 0:(j0,g) 1:(j0,c) 2:(j1,g) 3:(j1,c)
    int jl = 2*jg + (pairidx >> 1);
    int col = pairidx & 1;
    int j = (p & 63)*JPC + jl;
    float v;
    if (col == 0) {
        v = Wg[(size_t)(l*1024 + k)*512 + j];
    } else {
        v = (k < II) ? Wi[(size_t)(l*512 + k)*512 + j]
                     : Wh[(size_t)(l*512 + (k - II))*512 + j];
    }
    g_Wdup[idx] = v;
}

// Zero hidden state + counters (runs at the start of every replay).
__global__ void init_kernel(){
    int i = blockIdx.x * blockDim.x + threadIdx.x;
    if (i == 0){ g_c0 = 0u; g_c1 = 0u; }
    if (i < BB*HH){
        g_h0[0][i] = 0.f; g_h0[1][i] = 0.f; g_h0[2][i] = 0.f; g_h0[3][i] = 0.f;
        g_h1[0][i] = 0.f; g_h1[1][i] = 0.f;
    }
}

// Persistent kernel: 128 CTAs (one per SM), 256 threads (8 warps, 2 per SMSP),
// phases s=0..SS with DECOUPLED per-layer barriers:
//   phase s:  CTAs l==0 compute h0[s]   = gru(x[:,s,:], h0[s-1])   (s < SS)
//             CTAs l==1 compute h1[s-1] = gru(h0[s-1],  h1[s-2])   (s >= 1)
// h0 lives in a 4-deep ring (slot s&3), so layer-0 may run up to 3 phases
// ahead of layer-1. Wait conditions before phase s:
//   layer-0: c0 >= 64*s                  (own layer finished s-1)
//            c1 >= 64*(s-2)  [s>=3]      (layer-1 finished s-3: WAR on ring slot)
//   layer-1: c0 >= 64*s && c1 >= 64*s    (h0[s-1] ready; own h1 WAR)
// Inner loop: k-split (warp w owns k in [128w,128w+128)), (m,m+1)-paired FFMA2
// with a duplicated weight panel (no packdup MOVs): 4 LDS.128 + 16 FFMA2 per k.
__global__ void __launch_bounds__(TPB, 1)
persist_kernel(const float* __restrict__ x, const float* __restrict__ bg,
               const float* __restrict__ bi, float* __restrict__ out,
               int out_size)
{
    const int p = blockIdx.x;
    const int l = p >> 6;
    const int t = threadIdx.x;
    const int wid  = t >> 5;
    const int lane = t & 31;
    const int jg = lane >> 3;    // 0..3 : j-pair group (j = 2jg, 2jg+1)
    const int mg = lane & 7;     // 0..7 : m rows 4mg..4mg+3 and 32+4mg..+3
    const int sL = lane & 3;     // staging k-seg (k = 4sL..4sL+3 within chunk)
    const int mrL = lane >> 2;   // staging m-row part (0..7)

    extern __shared__ float smf[];
    float* ws   = smf;                              // [1024][32] duplicated weights
    float* bufs = smf + WS_FLOATS;                  // 16 x 1024 floats (2 per warp)
    ull*   px   = (ull*)(smf + WS_FLOATS + 2*NWARP*ABUF_FLOATS);  // [8][8][2][32]

    // ---- copy duplicated weight panel into SMEM once ----
    {
        const float4* gw = ((const float4*)g_Wdup) + (size_t)p * 8192;
        float4* w4 = (float4*)ws;
        #pragma unroll
        for (int it = 0; it < 32; ++it)
            w4[t + it*TPB] = gw[t + it*TPB];
    }
    __syncthreads();

    const int kb = wid * KRANGE;         // this warp's k base
    float* b0 = bufs + wid*2*ABUF_FLOATS;
    float* b1 = b0 + ABUF_FLOATS;

    const int jj_e = (t >> 4) & 7;           // epilogue j index 0..7 (threads 0..127)
    const int j = (p & 63)*JPC + jj_e;
    const float bgv = bg[l*HH + j];
    const float biv = bi[l*HH + j];

    #pragma unroll 1
    for (int s = 0; s <= SS; ++s){
        const bool active = !((l == 0 && s == SS) || (l == 1 && s == 0));
        if (active){
            int pb = s & 1;
            const float* h0prev  = g_h0[(s - 1) & 3];   // (-1)&3 == 3: initial zeros
            float*       h0out   = g_h0[s & 3];
            const float* h1prev2 = g_h1[pb];
            float*       h1out   = g_h1[pb ^ 1];

            // per-warp activation source (k range lies wholly in one matrix)
            const float* src; size_t stride;
            const float* hupd; float* hout;
            if (l == 0){
                if (kb < II){ src = x + (size_t)s*II + kb; stride = (size_t)SS*II; }
                else        { src = h0prev + (kb - II);    stride = HH; }
                hupd = h0prev;  hout = h0out;
            } else {
                if (kb < II){ src = h0prev + kb;           stride = HH; }
                else        { src = h1prev2 + (kb - II);   stride = HH; }
                hupd = h1prev2; hout = h1out;
            }

            // ---- warp-private staging: LDG.128 k-major -> swizzled [k][m] tile ----
            float4 pfv[8];
            auto ldg = [&](int c){
                const float* sc = src + c*KT + 4*sL;
                #pragma unroll
                for (int r = 0; r < 8; ++r){
                    int m = 8*r + mrL;
                    pfv[r] = *(const float4*)(sc + (size_t)m*stride);
                }
            };
            // store element i of pfv[r] (k = 4sL+i, m = 8r+mrL) at
            // row (4sL+i)*64, column ((m>>2) ^ sL)*4 + (m&3)
            auto sts = [&](float* buf){
                float* base = buf + 4*sL*64;
                #pragma unroll
                for (int r = 0; r < 8; ++r){
                    int m = 8*r + mrL;
                    float* d = base + (((m >> 2) ^ sL)*4 + (m & 3));
                    d[0]   = pfv[r].x;
                    d[64]  = pfv[r].y;
                    d[128] = pfv[r].z;
                    d[192] = pfv[r].w;
                }
            };

            // acc[wsel][psel]: wsel 0:(j0,gate) 1:(j0,cand) 2:(j1,gate) 3:(j1,cand)
            //                  psel 0:(m 4mg,4mg+1) 1:(4mg+2,4mg+3) 2:(32+4mg,+1) 3:(+2,+3)
            ull acc[4][4];
            #pragma unroll
            for (int a2 = 0; a2 < 4; ++a2)
                #pragma unroll
                for (int i = 0; i < 4; ++i) acc[a2][i] = 0ull;

            auto compute = [&](const float* buf, int c){
                const float* wd = ws + (size_t)(kb + c*KT)*32 + jg*8;
                #pragma unroll
                for (int kk = 0; kk < KT; ++kk){
                    const float* arow = buf + kk*64;
                    int gx = (mg ^ (kk >> 2)) << 2;
                    ulonglong2 aA = *(const ulonglong2*)(arow + gx);        // m 4mg..+3
                    ulonglong2 aB = *(const ulonglong2*)(arow + gx + 32);   // m 32+4mg..+3
                    ulonglong2 wA = *(const ulonglong2*)(wd + kk*32);       // (g,c) j0 dup
                    ulonglong2 wB = *(const ulonglong2*)(wd + kk*32 + 4);   // (g,c) j1 dup
                    acc[0][0]=ffma2(aA.x,wA.x,acc[0][0]); acc[0][1]=ffma2(aA.y,wA.x,acc[0][1]);
                    acc[0][2]=ffma2(aB.x,wA.x,acc[0][2]); acc[0][3]=ffma2(aB.y,wA.x,acc[0][3]);
                    acc[1][0]=ffma2(aA.x,wA.y,acc[1][0]); acc[1][1]=ffma2(aA.y,wA.y,acc[1][1]);
                    acc[1][2]=ffma2(aB.x,wA.y,acc[1][2]); acc[1][3]=ffma2(aB.y,wA.y,acc[1][3]);
                    acc[2][0]=ffma2(aA.x,wB.x,acc[2][0]); acc[2][1]=ffma2(aA.y,wB.x,acc[2][1]);
                    acc[2][2]=ffma2(aB.x,wB.x,acc[2][2]); acc[2][3]=ffma2(aB.y,wB.x,acc[2][3]);
                    acc[3][0]=ffma2(aA.x,wB.y,acc[3][0]); acc[3][1]=ffma2(aA.y,wB.y,acc[3][1]);
                    acc[3][2]=ffma2(aB.x,wB.y,acc[3][2]); acc[3][3]=ffma2(aB.y,wB.y,acc[3][3]);
                }
            };

            // warp-private pipeline: no CTA syncs in the mainloop
            ldg(0); sts(b0); __syncwarp();
            #pragma unroll 1
            for (int c = 0; c < NCHUNK; ++c){
                if (c + 1 < NCHUNK) ldg(c + 1);
                compute((c & 1) ? b1 : b0, c);
                if (c + 1 < NCHUNK) sts((c & 1) ? b0 : b1);
                __syncwarp();
            }

            // ---- cross-warp k-reduction through SMEM ----
            // px[w][j][col][mpair]: ull = (m_even, m_odd) f32 pair
            __syncthreads();
            #pragma unroll
            for (int j2 = 0; j2 < 2; ++j2){
                ull* pg = px + (size_t)(((wid*8 + 2*jg + j2)*2 + 0))*32;
                ull* pc = px + (size_t)(((wid*8 + 2*jg + j2)*2 + 1))*32;
                *(ulonglong2*)(pg + 2*mg)      = make_ulonglong2(acc[2*j2][0],   acc[2*j2][1]);
                *(ulonglong2*)(pg + 16 + 2*mg) = make_ulonglong2(acc[2*j2][2],   acc[2*j2][3]);
                *(ulonglong2*)(pc + 2*mg)      = make_ulonglong2(acc[2*j2+1][0], acc[2*j2+1][1]);
                *(ulonglong2*)(pc + 16 + 2*mg) = make_ulonglong2(acc[2*j2+1][2], acc[2*j2+1][3]);
            }
            __syncthreads();

            // ---- epilogue: sum 8 warp partials (packed f32x2 adds), GRU update ----
            if (t < 128){
                const int m0 = (t & 15) * 4;    // 4 batch rows
                const int mp = m0 >> 1;         // mpair base (even)
                ull g01 = 0, g23 = 0, c01 = 0, c23 = 0;
                #pragma unroll
                for (int w = 0; w < NWARP; ++w){
                    const ull* pg = px + (size_t)(((w*8 + jj_e)*2 + 0))*32 + mp;
                    const ull* pc = px + (size_t)(((w*8 + jj_e)*2 + 1))*32 + mp;
                    ulonglong2 g2 = *(const ulonglong2*)pg;
                    ulonglong2 c2 = *(const ulonglong2*)pc;
                    g01 = addf2(g01, g2.x); g23 = addf2(g23, g2.y);
                    c01 = addf2(c01, c2.x); c23 = addf2(c23, c2.y);
                }
                float gv[4], cv[4];
                unpack2(g01, gv[0], gv[1]); unpack2(g23, gv[2], gv[3]);
                unpack2(c01, cv[0], cv[1]); unpack2(c23, cv[2], cv[3]);
                #pragma unroll
                for (int r = 0; r < 4; ++r){
                    int m = m0 + r;
                    float zin = gv[r] + bgv;
                    float z   = __fdividef(1.f, 1.f + __expf(-zin));
                    float cin = cv[r] + biv;
                    float av  = fabsf(cin);
                    float e   = __expf(-2.f*av);
                    float cd  = copysignf(__fdividef(1.f - e, 1.f + e), cin);
                    float hp  = hupd[(size_t)m*HH + j];
                    float hn  = hp + z*(cd - hp);
                    hout[(size_t)m*HH + j] = hn;
                    if (l == 1)
                        out[(size_t)m*SS*HH + (size_t)(s-1)*HH + j] = hn;
                }
            }
        }

        // ---- decoupled per-layer barriers ----
        __syncthreads();
        if (t == 0){
            __threadfence();
            atomicAdd(l == 0 ? &g_c0 : &g_c1, 1u);
            unsigned s1 = (unsigned)s + 1u;
            if (s1 <= SS){
                if (l == 0){
                    wait_ge(&g_c0, 64u*s1);
                    if (s1 >= 3u) wait_ge(&g_c1, 64u*(s1 - 2u));
                } else {
                    wait_ge(&g_c0, 64u*s1);
                    wait_ge(&g_c1, 64u*s1);
                }
            } else {
                // final full join before the tail
                wait_ge(&g_c0, 64u*(SS + 1u));
                wait_ge(&g_c1, 64u*(SS + 1u));
            }
        }
        __syncthreads();
    }

    // ---- tail: final hidden states appended after output ----
    // h0[S-1] lives in ring slot (SS-1)&3 = 3; h1[S-1] in g_h1[1].
    long long base = (long long)BB*SS*HH;
    if (base + 2LL*BB*HH <= (long long)out_size){
        for (int i = p*TPB + t; i < BB*HH; i += NPANEL*TPB){
            out[base + i]         = g_h0[3][i];
            out[base + BB*HH + i] = g_h1[1][i];
        }
    }
}

extern "C" void kernel_launch(void* const* d_in, const int* in_sizes, int n_in,
                              void* d_out, int out_size)
{
    const float* x  = (const float*)d_in[0];
    const float* Wg = (const float*)d_in[1];
    const float* bg = (const float*)d_in[2];
    const float* Wi = (const float*)d_in[3];
    const float* bi = (const float*)d_in[4];
    const float* Wh = (const float*)d_in[5];
    float* out = (float*)d_out;

    cudaFuncSetAttribute(persist_kernel, cudaFuncAttributeMaxDynamicSharedMemorySize, SMEM_BYTES);

    prep_kernel<<<(NPANEL*1024*32 + 255)/256, 256>>>(Wg, Wi, Wh);
    init_kernel<<<(BB*HH + 255)/256, 256>>>();
    persist_kernel<<<NPANEL, TPB, SMEM_BYTES>>>(x, bg, bi, out, out_size);
}